// round 3
// baseline (speedup 1.0000x reference)
#include <cuda_runtime.h>
#include <cstdint>
#include <cstddef>
#include <cub/cub.cuh>

// Problem shape (fixed by the reference setup_inputs): B=4, H=16, L=1024, D=64
constexpr int Bc = 4;
constexpr int Hc = 16;
constexpr int Lc = 1024;
constexpr int Dc = 64;

constexpr int THREADS = 256;
constexpr int IPT = 4;               // 256*4 = 1024 = L
constexpr int NCOL = Bc * Hc * Dc;   // 4096 (bh, d) columns

// Compact scatter worklist produced by the sort kernel, consumed by scatter.
__device__ float g_vals[(size_t)NCOL * Lc];   // exp(-(dq)^2)/D
__device__ int   g_lin [(size_t)NCOL * Lc];   // qi*1024 + kj  (within-bh cell)

// ---------------------------------------------------------------------------
// Kernel 1: one block per (bh, d) column pair.
//  - zero-fills its own 64KB slice of out (posted STG.128s; the DRAM writes
//    drain underneath the L1-bound sort work)
//  - radix-sorts (value, seq-index) for the q column and the k column
//  - emits matched-rank (value, packed index) pairs to the scratch worklist
// ---------------------------------------------------------------------------
__global__ __launch_bounds__(THREADS, 5)
void sort_pair_kernel(const float* __restrict__ q,
                      const float* __restrict__ k,
                      float* __restrict__ out)
{
    const int bid = blockIdx.x;
    const int t   = threadIdx.x;

    // ---- zero my 16384-float slice of out (4096 float4s / 256 threads) ----
    {
        float4* oz = reinterpret_cast<float4*>(out) + (size_t)bid * 4096;
        const float4 z4 = make_float4(0.f, 0.f, 0.f, 0.f);
#pragma unroll
        for (int i = 0; i < 16; i++) oz[t + i * THREADS] = z4;
    }

    using BlockSort = cub::BlockRadixSort<float, THREADS, IPT, int>;
    __shared__ typename BlockSort::TempStorage sort_ts;
    __shared__ float qs_val[Lc];
    __shared__ int   qs_idx[Lc];

    const int d  = bid & (Dc - 1);
    const int bh = bid >> 6;         // Dc == 64

    const float* qcol = q + (size_t)bh * Lc * Dc + d;
    const float* kcol = k + (size_t)bh * Lc * Dc + d;

    float keys[IPT];
    int   vals[IPT];

    // ---- sort q column ----
#pragma unroll
    for (int i = 0; i < IPT; i++) {
        int r = t * IPT + i;
        keys[i] = qcol[(size_t)r * Dc];
        vals[i] = r;
    }
    BlockSort(sort_ts).Sort(keys, vals);

#pragma unroll
    for (int i = 0; i < IPT; i++) {
        int r = t * IPT + i;
        qs_val[r] = keys[i];
        qs_idx[r] = vals[i];
    }
    __syncthreads();   // guards temp-storage reuse + qs visibility

    // ---- sort k column ----
#pragma unroll
    for (int i = 0; i < IPT; i++) {
        int r = t * IPT + i;
        keys[i] = kcol[(size_t)r * Dc];
        vals[i] = r;
    }
    BlockSort(sort_ts).Sort(keys, vals);

    // ---- emit matched-rank pairs (thread t holds ranks t*4..t*4+3 of both) --
    float v4[IPT];
    int   l4[IPT];
    constexpr float inv_D = 1.0f / (float)Dc;
#pragma unroll
    for (int i = 0; i < IPT; i++) {
        int r = t * IPT + i;
        float dq = qs_val[r] - keys[i];
        v4[i] = __expf(-dq * dq) * inv_D;
        l4[i] = (qs_idx[r] << 10) | vals[i];
    }
    size_t base = (size_t)bid * Lc + (size_t)t * IPT;   // 16B aligned
    *reinterpret_cast<float4*>(g_vals + base) = *reinterpret_cast<float4*>(v4);
    *reinterpret_cast<int4*>  (g_lin  + base) = *reinterpret_cast<int4*>(l4);
}

// ---------------------------------------------------------------------------
// Kernel 2: consume the worklist — mask check + REDG scatter-add.
// 4 entries per thread (vectorized worklist loads). All 4 entries of a thread
// share the same bh (65536 entries per bh, divisible by 4).
// ---------------------------------------------------------------------------
__global__ __launch_bounds__(THREADS)
void scatter_kernel(const int* __restrict__ mask,
                    float* __restrict__ out)
{
    const int e4 = blockIdx.x * THREADS + threadIdx.x;   // 0 .. 1048575
    float4 v = *reinterpret_cast<const float4*>(g_vals + (size_t)e4 * 4);
    int4   l = *reinterpret_cast<const int4*>  (g_lin  + (size_t)e4 * 4);

    const int    bh   = e4 >> 14;                 // (e4*4) / 65536
    const size_t base = (size_t)bh << 20;         // bh * 1024 * 1024

    size_t o0 = base + l.x;
    size_t o1 = base + l.y;
    size_t o2 = base + l.z;
    size_t o3 = base + l.w;
    if (mask[o0] == 0) atomicAdd(out + o0, v.x);
    if (mask[o1] == 0) atomicAdd(out + o1, v.y);
    if (mask[o2] == 0) atomicAdd(out + o2, v.z);
    if (mask[o3] == 0) atomicAdd(out + o3, v.w);
}

extern "C" void kernel_launch(void* const* d_in, const int* in_sizes, int n_in,
                              void* d_out, int out_size)
{
    const float* q    = (const float*)d_in[0];
    const float* k    = (const float*)d_in[1];
    const int*   mask = (const int*)d_in[2];
    float*       out  = (float*)d_out;

    sort_pair_kernel<<<NCOL, THREADS>>>(q, k, out);
    scatter_kernel<<<(NCOL * Lc) / (THREADS * 4), THREADS>>>(mask, out);
}

// round 6
// speedup vs baseline: 1.8111x; 1.8111x over previous
#include <cuda_runtime.h>
#include <cstdint>
#include <cstddef>
#include <cub/cub.cuh>

// Problem shape (fixed by the reference setup_inputs): B=4, H=16, L=1024, D=64
constexpr int Bc = 4;
constexpr int Hc = 16;
constexpr int Lc = 1024;
constexpr int Dc = 64;
constexpr int NBH  = Bc * Hc;        // 64
constexpr int NCOL = NBH * Dc;       // 4096 (bh, d) columns

constexpr int THREADS = 256;
constexpr int IPT = 4;               // 256*4 = 1024 = L

// Transposed copies: [bh][d][L] so each sort block reads a contiguous column.
__device__ float g_qT[(size_t)NCOL * Lc];
__device__ float g_kT[(size_t)NCOL * Lc];

// ---------------------------------------------------------------------------
// Kernel A: transpose q,k into [bh][d][L] scratch AND zero the output.
// grid = 4096 blocks of 256 threads (viewed as 32x8).
//   bid -> dt (2 tiles of 32 dims) | rt (32 tiles of 32 rows) | bh (64)
// DRAM: 64MB rd + 64MB wr (transpose) + 256MB wr (zero)  ->  ~60us.
// ---------------------------------------------------------------------------
__global__ __launch_bounds__(THREADS)
void prep_kernel(const float* __restrict__ q,
                 const float* __restrict__ k,
                 float* __restrict__ out)
{
    __shared__ float tile[32][33];

    const int bid = blockIdx.x;
    const int dt  = bid & 1;
    const int rt  = (bid >> 1) & 31;
    const int bh  = bid >> 6;

    const int x = threadIdx.x & 31;    // 0..31
    const int y = threadIdx.x >> 5;    // 0..7

    const int r0 = rt * 32;
    const int d0 = dt * 32;
    const size_t sbase = (size_t)bh * Lc * Dc;

    // ---- zero my 64KB slice of out (coalesced STG.128, posted) ----
    {
        float4* oz = reinterpret_cast<float4*>(out) + (size_t)bid * 4096;
        const float4 z4 = make_float4(0.f, 0.f, 0.f, 0.f);
#pragma unroll
        for (int i = 0; i < 16; i++) oz[threadIdx.x + i * THREADS] = z4;
    }

    // ---- transpose q tile ----
#pragma unroll
    for (int i = 0; i < 4; i++) {
        int row = y + i * 8;
        tile[row][x] = q[sbase + (size_t)(r0 + row) * Dc + d0 + x];
    }
    __syncthreads();
#pragma unroll
    for (int i = 0; i < 4; i++) {
        int dr = y + i * 8;
        g_qT[((size_t)bh * Dc + d0 + dr) * Lc + r0 + x] = tile[x][dr];
    }
    __syncthreads();

    // ---- transpose k tile ----
#pragma unroll
    for (int i = 0; i < 4; i++) {
        int row = y + i * 8;
        tile[row][x] = k[sbase + (size_t)(r0 + row) * Dc + d0 + x];
    }
    __syncthreads();
#pragma unroll
    for (int i = 0; i < 4; i++) {
        int dr = y + i * 8;
        g_kT[((size_t)bh * Dc + d0 + dr) * Lc + r0 + x] = tile[x][dr];
    }
}

// ---------------------------------------------------------------------------
// Kernel B: one block per (bh, d). Coalesced float4 column loads, exact
// full-precision radix sort of (float key, ushort index), pair equal ranks,
// inline mask check + REDG scatter (hidden under other blocks' sorts).
// ---------------------------------------------------------------------------
__global__ __launch_bounds__(THREADS)
void sort_scatter_kernel(const int* __restrict__ mask,
                         float* __restrict__ out)
{
    using BlockSort = cub::BlockRadixSort<float, THREADS, IPT, unsigned short>;

    __shared__ typename BlockSort::TempStorage sort_ts;
    __shared__ float          qs_val[Lc];
    __shared__ unsigned short qs_idx[Lc];

    const int bid = blockIdx.x;            // == (bh*64 + d)
    const int bh  = bid >> 6;
    const int t   = threadIdx.x;

    const float* qcol = g_qT + (size_t)bid * Lc;
    const float* kcol = g_kT + (size_t)bid * Lc;

    float          keys[IPT];
    unsigned short vals[IPT];

    // ---- sort q column (coalesced vector load) ----
    {
        float4 v4 = reinterpret_cast<const float4*>(qcol)[t];
        keys[0] = v4.x; keys[1] = v4.y; keys[2] = v4.z; keys[3] = v4.w;
    }
#pragma unroll
    for (int i = 0; i < IPT; i++) vals[i] = (unsigned short)(t * IPT + i);
    BlockSort(sort_ts).Sort(keys, vals);

#pragma unroll
    for (int i = 0; i < IPT; i++) {
        int r = t * IPT + i;
        qs_val[r] = keys[i];
        qs_idx[r] = vals[i];
    }
    __syncthreads();   // guards temp-storage reuse + qs visibility

    // ---- sort k column ----
    {
        float4 v4 = reinterpret_cast<const float4*>(kcol)[t];
        keys[0] = v4.x; keys[1] = v4.y; keys[2] = v4.z; keys[3] = v4.w;
    }
#pragma unroll
    for (int i = 0; i < IPT; i++) vals[i] = (unsigned short)(t * IPT + i);
    BlockSort(sort_ts).Sort(keys, vals);

    // ---- pair equal ranks, inline mask check + scatter-add ----
    const int* mrow = mask + (size_t)bh * Lc * Lc;
    float* orow = out + (size_t)bh * Lc * Lc;

    constexpr float inv_D = 1.0f / (float)Dc;

#pragma unroll
    for (int i = 0; i < IPT; i++) {
        int r = t * IPT + i;
        float dq = qs_val[r] - keys[i];
        float v  = __expf(-dq * dq) * inv_D;
        int   qi = qs_idx[r];
        int   kj = vals[i];
        size_t off = ((size_t)qi << 10) | (unsigned)kj;
        if (mrow[off] == 0) {
            atomicAdd(orow + off, v);   // no return use -> REDG
        }
    }
}

extern "C" void kernel_launch(void* const* d_in, const int* in_sizes, int n_in,
                              void* d_out, int out_size)
{
    const float* q    = (const float*)d_in[0];
    const float* k    = (const float*)d_in[1];
    const int*   mask = (const int*)d_in[2];
    float*       out  = (float*)d_out;

    prep_kernel<<<NCOL, THREADS>>>(q, k, out);
    sort_scatter_kernel<<<NCOL, THREADS>>>(mask, out);
}

// round 7
// speedup vs baseline: 2.9178x; 1.6111x over previous
#include <cuda_runtime.h>
#include <cstdint>
#include <cstddef>

// Problem shape (fixed by the reference setup_inputs): B=4, H=16, L=1024, D=64
constexpr int Lc = 1024;
constexpr int Dc = 64;
constexpr int NBH  = 64;             // B*H
constexpr int NCOL = NBH * Dc;       // 4096 (bh, d) columns

constexpr int THREADS = 256;

// Transposed copies: [bh][d][L] so each sort block reads a contiguous column.
__device__ float g_qT[(size_t)NCOL * Lc];
__device__ float g_kT[(size_t)NCOL * Lc];

// ---------------------------------------------------------------------------
// Kernel A: transpose q,k into [bh][d][L] scratch AND zero the output.
// (unchanged from the R6 passing kernel)
// ---------------------------------------------------------------------------
__global__ __launch_bounds__(THREADS)
void prep_kernel(const float* __restrict__ q,
                 const float* __restrict__ k,
                 float* __restrict__ out)
{
    __shared__ float tile[32][33];

    const int bid = blockIdx.x;
    const int dt  = bid & 1;
    const int rt  = (bid >> 1) & 31;
    const int bh  = bid >> 6;

    const int x = threadIdx.x & 31;
    const int y = threadIdx.x >> 5;

    const int r0 = rt * 32;
    const int d0 = dt * 32;
    const size_t sbase = (size_t)bh * Lc * Dc;

    {   // zero my 64KB slice of out
        float4* oz = reinterpret_cast<float4*>(out) + (size_t)bid * 4096;
        const float4 z4 = make_float4(0.f, 0.f, 0.f, 0.f);
#pragma unroll
        for (int i = 0; i < 16; i++) oz[threadIdx.x + i * THREADS] = z4;
    }

#pragma unroll
    for (int i = 0; i < 4; i++) {
        int row = y + i * 8;
        tile[row][x] = q[sbase + (size_t)(r0 + row) * Dc + d0 + x];
    }
    __syncthreads();
#pragma unroll
    for (int i = 0; i < 4; i++) {
        int dr = y + i * 8;
        g_qT[((size_t)bh * Dc + d0 + dr) * Lc + r0 + x] = tile[x][dr];
    }
    __syncthreads();

#pragma unroll
    for (int i = 0; i < 4; i++) {
        int row = y + i * 8;
        tile[row][x] = k[sbase + (size_t)(r0 + row) * Dc + d0 + x];
    }
    __syncthreads();
#pragma unroll
    for (int i = 0; i < 4; i++) {
        int dr = y + i * 8;
        g_kT[((size_t)bh * Dc + d0 + dr) * Lc + r0 + x] = tile[x][dr];
    }
}

// ---------------------------------------------------------------------------
// Kernel B: one block per (bh, d). Distribution (counting) sort:
//   bucket = floor(1024 * Phi(v))  (erff, monotone, ~uniform for N(0,1))
//   histogram -> block scan -> atomic-cursor scatter -> exact within-bucket
//   fixup by lexicographic (value, index)  == stable argsort.
// Phase 0 sorts q into (qv, qi); phase 1 sorts k and, at final-rank
// resolution, pairs with (qv[r], qi[r]) and does the inline mask + REDG
// scatter (DRAM tail hides under other blocks' sorts across waves).
// ---------------------------------------------------------------------------
__global__ __launch_bounds__(THREADS)
void sort_scatter_kernel(const int* __restrict__ mask,
                         float* __restrict__ out)
{
    __shared__ float          qv[Lc];
    __shared__ unsigned short qi[Lc];
    __shared__ float          wval[Lc];
    __shared__ unsigned short widx[Lc];
    __shared__ unsigned short wbkt[Lc];
    __shared__ int            cursor[Lc];   // histogram, then scatter cursor
    __shared__ int            P0[Lc + 1];   // exclusive prefix (run bounds)
    __shared__ int            wtot[8];

    const int bid  = blockIdx.x;           // == bh*64 + d
    const int bh   = bid >> 6;
    const int t    = threadIdx.x;
    const int lane = t & 31;
    const int w    = t >> 5;

    const int* mrow = mask + (size_t)bh * Lc * Lc;
    float*     orow = out  + (size_t)bh * Lc * Lc;
    constexpr float inv_D = 1.0f / (float)Dc;

    for (int phase = 0; phase < 2; phase++) {
        const float* col = (phase == 0 ? g_qT : g_kT) + (size_t)bid * Lc;

        // ---- load 4 values, compute buckets ----
        float4 v4 = reinterpret_cast<const float4*>(col)[t];
        float v[4] = {v4.x, v4.y, v4.z, v4.w};
        int   b[4];
#pragma unroll
        for (int i = 0; i < 4; i++) {
            float u = 0.5f * erff(v[i] * 0.70710678f) + 0.5f;
            int bi = (int)(u * 1024.0f);
            b[i] = bi < 0 ? 0 : (bi > 1023 ? 1023 : bi);
        }

        // ---- histogram ----
#pragma unroll
        for (int i = 0; i < 4; i++) cursor[t + THREADS * i] = 0;
        __syncthreads();
#pragma unroll
        for (int i = 0; i < 4; i++) atomicAdd(&cursor[b[i]], 1);
        __syncthreads();

        // ---- exclusive scan of 1024 bins (4 contiguous bins / thread) ----
        int c0 = cursor[4 * t + 0];
        int c1 = cursor[4 * t + 1];
        int c2 = cursor[4 * t + 2];
        int c3 = cursor[4 * t + 3];
        int s  = c0 + c1 + c2 + c3;
        int incl = s;
#pragma unroll
        for (int o = 1; o < 32; o <<= 1) {
            int n = __shfl_up_sync(0xFFFFFFFFu, incl, o);
            if (lane >= o) incl += n;
        }
        if (lane == 31) wtot[w] = incl;
        __syncthreads();
        if (t == 0) {
            int acc = 0;
#pragma unroll
            for (int i = 0; i < 8; i++) { int x = wtot[i]; wtot[i] = acc; acc += x; }
        }
        __syncthreads();
        int excl = wtot[w] + (incl - s);
        P0[4 * t + 0] = excl;
        P0[4 * t + 1] = excl + c0;
        P0[4 * t + 2] = excl + c0 + c1;
        P0[4 * t + 3] = excl + c0 + c1 + c2;
        cursor[4 * t + 0] = excl;
        cursor[4 * t + 1] = excl + c0;
        cursor[4 * t + 2] = excl + c0 + c1;
        cursor[4 * t + 3] = excl + c0 + c1 + c2;
        if (t == 0) P0[Lc] = Lc;
        __syncthreads();

        // ---- scatter into bucket-ordered arrays ----
#pragma unroll
        for (int i = 0; i < 4; i++) {
            int pos = atomicAdd(&cursor[b[i]], 1);
            wval[pos] = v[i];
            widx[pos] = (unsigned short)(4 * t + i);
            wbkt[pos] = (unsigned short)b[i];
        }
        __syncthreads();

        // ---- exact fixup: rank within bucket by (value, index) ----
#pragma unroll
        for (int i = 0; i < 4; i++) {
            int p = t + THREADS * i;
            float vv = wval[p];
            int   ii = widx[p];
            int   bb = wbkt[p];
            int start = P0[bb];
            int end   = P0[bb + 1];
            int r = p;                         // len==1 -> p == start
            if (end - start > 1) {
                r = start;
                for (int j = start; j < end; j++) {
                    float vj = wval[j];
                    if (vj < vv || (vj == vv && widx[j] < ii)) r++;
                }
            }
            if (phase == 0) {
                qv[r] = vv;
                qi[r] = (unsigned short)ii;
            } else {
                float dq  = qv[r] - vv;
                float val = __expf(-dq * dq) * inv_D;
                size_t off = ((size_t)qi[r] << 10) | (unsigned)ii;
                if (mrow[off] == 0) {
                    atomicAdd(orow + off, val);   // no return use -> REDG
                }
            }
        }
        __syncthreads();   // qv/qi complete before k-phase; arrays reused
    }
}

extern "C" void kernel_launch(void* const* d_in, const int* in_sizes, int n_in,
                              void* d_out, int out_size)
{
    const float* q    = (const float*)d_in[0];
    const float* k    = (const float*)d_in[1];
    const int*   mask = (const int*)d_in[2];
    float*       out  = (float*)d_out;

    prep_kernel<<<NCOL, THREADS>>>(q, k, out);
    sort_scatter_kernel<<<NCOL, THREADS>>>(mask, out);
}